// round 16
// baseline (speedup 1.0000x reference)
#include <cuda_runtime.h>
#include <cstdint>

// BaseVectorQuantizer, exact: dist_k = fp32( fp32(||x||^2+||e_k||^2) - 2*dot ).
// V=2, row-major codebook in smem, broadcast LDS.128 -> 4 fma.rn.f32x2.
// Explicit SW pipeline: 4 rotating register quarter-buffers (8 ull each);
// loads run 2 quarters (~70 cyc) ahead of their consumers.
// Per-chain accumulation order identical to the R13/R15 zero-flip chain.

#define NUM_K 1024
#define DIM   64
#define CHUNK 256
#define TPB   128
#define HW    4096
#define NVEC  131072
#define VPB   256

typedef unsigned long long ull_t;

__device__ float g_esq[NUM_K];

__global__ void esq_kernel(const float* __restrict__ cb) {
    int k = blockIdx.x * blockDim.x + threadIdx.x;
    if (k < NUM_K) {
        float s = 0.f;
        #pragma unroll
        for (int i = 0; i < DIM; i++) {
            float v = cb[k * DIM + i];
            s = __fadd_rn(s, __fmul_rn(v, v));
        }
        g_esq[k] = s;
    }
}

// load one quarter (16 floats = 64 B) of a code row; gq = global quarter index
#define LOADQ(B, gq) do {                                                        \
    const uint32_t qa = se_base + ((((uint32_t)(gq)) & (CHUNK * 4 - 1)) << 6);   \
    asm("ld.shared.v2.u64 {%0,%1},[%2];" : "=l"(B[0]), "=l"(B[1]) : "r"(qa));    \
    asm("ld.shared.v2.u64 {%0,%1},[%2];" : "=l"(B[2]), "=l"(B[3]) : "r"(qa + 16)); \
    asm("ld.shared.v2.u64 {%0,%1},[%2];" : "=l"(B[4]), "=l"(B[5]) : "r"(qa + 32)); \
    asm("ld.shared.v2.u64 {%0,%1},[%2];" : "=l"(B[6]), "=l"(B[7]) : "r"(qa + 48)); \
} while (0)

// consume one quarter: d4 groups 4q..4q+3, same chain order as R13/R15
#define FMAQ(B, q) do {                                                          \
    _Pragma("unroll")                                                            \
    for (int d = 0; d < 4; d++) {                                                \
        asm("fma.rn.f32x2 %0, %1, %2, %0;"                                       \
            : "+l"(a0) : "l"(xA2[2 * (4 * (q) + d)]),     "l"(B[2 * d]));        \
        asm("fma.rn.f32x2 %0, %1, %2, %0;"                                       \
            : "+l"(b0) : "l"(xB2[2 * (4 * (q) + d)]),     "l"(B[2 * d]));        \
        asm("fma.rn.f32x2 %0, %1, %2, %0;"                                       \
            : "+l"(a1) : "l"(xA2[2 * (4 * (q) + d) + 1]), "l"(B[2 * d + 1]));    \
        asm("fma.rn.f32x2 %0, %1, %2, %0;"                                       \
            : "+l"(b1) : "l"(xB2[2 * (4 * (q) + d) + 1]), "l"(B[2 * d + 1]));    \
    }                                                                            \
} while (0)

__global__ __launch_bounds__(TPB, 2) void vq_kernel(const float* __restrict__ x_in,
                                                    const float* __restrict__ cb,
                                                    float* __restrict__ out) {
    __shared__ __align__(16) float se[CHUNK * DIM];   // 64 KB row-major
    __shared__ float sesq[CHUNK];

    const int t    = threadIdx.x;
    const int base = blockIdx.x * VPB;
    const int b    = base >> 12;
    const int sA   = (base & (HW - 1)) + t;
    const float* xpA = x_in + (size_t)b * (DIM * HW) + sA;
    const float* xpB = xpA + TPB;

    // x for both vectors as natural packed f32x2 dim-pairs; xsq sequential fp32
    ull_t xA2[DIM / 2], xB2[DIM / 2];
    float xsqA = 0.f, xsqB = 0.f;
    #pragma unroll
    for (int p = 0; p < DIM / 2; p++) {
        float a0f = xpA[(2 * p) * HW], a1f = xpA[(2 * p + 1) * HW];
        float c0f = xpB[(2 * p) * HW], c1f = xpB[(2 * p + 1) * HW];
        xsqA = __fadd_rn(xsqA, __fmul_rn(a0f, a0f));
        xsqA = __fadd_rn(xsqA, __fmul_rn(a1f, a1f));
        xsqB = __fadd_rn(xsqB, __fmul_rn(c0f, c0f));
        xsqB = __fadd_rn(xsqB, __fmul_rn(c1f, c1f));
        asm("mov.b64 %0, {%1, %2};" : "=l"(xA2[p]) : "f"(a0f), "f"(a1f));
        asm("mov.b64 %0, {%1, %2};" : "=l"(xB2[p]) : "f"(c0f), "f"(c1f));
    }

    uint32_t se_base;
    asm("{ .reg .u64 t; cvta.to.shared.u64 t, %1; cvt.u32.u64 %0, t; }"
        : "=r"(se_base) : "l"(se));

    float bestA = 3.4e38f, bestB = 3.4e38f;
    int   bkA = 0, bkB = 0;

    for (int c = 0; c < NUM_K / CHUNK; c++) {
        __syncthreads();
        const float4* src = reinterpret_cast<const float4*>(cb + c * CHUNK * DIM);
        float4* dst = reinterpret_cast<float4*>(se);
        #pragma unroll
        for (int j = 0; j < (CHUNK * DIM / 4) / TPB; j++)
            dst[j * TPB + t] = src[j * TPB + t];
        #pragma unroll
        for (int j = 0; j < CHUNK / TPB; j++)
            sesq[j * TPB + t] = g_esq[c * CHUNK + j * TPB + t];
        __syncthreads();

        ull_t eb0[8], eb1[8], eb2[8], eb3[8];
        LOADQ(eb0, 0);                       // prologue: quarters 0,1 of code 0
        LOADQ(eb1, 1);

        #pragma unroll 1
        for (int k = 0; k < CHUNK; k++) {
            ull_t a0 = 0ull, a1 = 0ull, b0 = 0ull, b1 = 0ull;
            const int G = k * 4;
            LOADQ(eb2, G + 2);  FMAQ(eb0, 0);    // loads lead consumers by 2 steps
            LOADQ(eb3, G + 3);  FMAQ(eb1, 1);
            LOADQ(eb0, G + 4);  FMAQ(eb2, 2);    // G+4 = quarter 0 of code k+1
            LOADQ(eb1, G + 5);  FMAQ(eb3, 3);

            ull_t sa, sb;
            asm("add.rn.f32x2 %0, %1, %2;" : "=l"(sa) : "l"(a0), "l"(a1));
            asm("add.rn.f32x2 %0, %1, %2;" : "=l"(sb) : "l"(b0), "l"(b1));
            float alo, ahi, blo, bhi;
            asm("mov.b64 {%0, %1}, %2;" : "=f"(alo), "=f"(ahi) : "l"(sa));
            asm("mov.b64 {%0, %1}, %2;" : "=f"(blo), "=f"(bhi) : "l"(sb));
            const float esq  = sesq[k];
            const float dotA = __fadd_rn(alo, ahi);
            const float dotB = __fadd_rn(blo, bhi);
            // dist = round(T - 2*dot), T = round(xsq+esq); 2*dot exact ->
            // fmaf(-2,dot,T) rounds once == reference fsub(T, 2dot)
            const float dA = fmaf(-2.f, dotA, __fadd_rn(xsqA, esq));
            const float dB = fmaf(-2.f, dotB, __fadd_rn(xsqB, esq));
            const int kk = c * CHUNK + k;
            bool pA = dA < bestA;            // branchless, ascending-k tie-break
            bool pB = dB < bestB;
            bestA = pA ? dA : bestA;  bkA = pA ? kk : bkA;
            bestB = pB ? dB : bestB;  bkB = pB ? kk : bkB;
        }
    }

    // STE epilogue: out = x + (e - x) fp32, BCHW scatter
    const float4* rowA = reinterpret_cast<const float4*>(cb + (size_t)bkA * DIM);
    const float4* rowB = reinterpret_cast<const float4*>(cb + (size_t)bkB * DIM);
    float* opA = out + (size_t)b * (DIM * HW) + sA;
    float* opB = opA + TPB;
    #pragma unroll
    for (int j = 0; j < DIM / 4; j++) {
        float4 qA = __ldg(&rowA[j]);
        float4 qB = __ldg(&rowB[j]);
        float a0f, a1f, a2f, a3f, c0f, c1f, c2f, c3f;
        asm("mov.b64 {%0, %1}, %2;" : "=f"(a0f), "=f"(a1f) : "l"(xA2[2 * j]));
        asm("mov.b64 {%0, %1}, %2;" : "=f"(a2f), "=f"(a3f) : "l"(xA2[2 * j + 1]));
        asm("mov.b64 {%0, %1}, %2;" : "=f"(c0f), "=f"(c1f) : "l"(xB2[2 * j]));
        asm("mov.b64 {%0, %1}, %2;" : "=f"(c2f), "=f"(c3f) : "l"(xB2[2 * j + 1]));
        opA[(4 * j + 0) * HW] = __fadd_rn(a0f, __fsub_rn(qA.x, a0f));
        opA[(4 * j + 1) * HW] = __fadd_rn(a1f, __fsub_rn(qA.y, a1f));
        opA[(4 * j + 2) * HW] = __fadd_rn(a2f, __fsub_rn(qA.z, a2f));
        opA[(4 * j + 3) * HW] = __fadd_rn(a3f, __fsub_rn(qA.w, a3f));
        opB[(4 * j + 0) * HW] = __fadd_rn(c0f, __fsub_rn(qB.x, c0f));
        opB[(4 * j + 1) * HW] = __fadd_rn(c1f, __fsub_rn(qB.y, c1f));
        opB[(4 * j + 2) * HW] = __fadd_rn(c2f, __fsub_rn(qB.z, c2f));
        opB[(4 * j + 3) * HW] = __fadd_rn(c3f, __fsub_rn(qB.w, c3f));
    }
}

extern "C" void kernel_launch(void* const* d_in, const int* in_sizes, int n_in,
                              void* d_out, int out_size) {
    const float* x  = (const float*)d_in[0];
    const float* cb = (const float*)d_in[1];
    if (n_in >= 2 && in_sizes[0] == NUM_K * DIM && in_sizes[1] == NVEC * DIM) {
        const float* t = x; x = cb; cb = t;
    }
    float* out = (float*)d_out;

    esq_kernel<<<(NUM_K + 127) / 128, 128>>>(cb);
    vq_kernel<<<NVEC / VPB, TPB>>>(x, cb, out);
}

// round 17
// speedup vs baseline: 1.0313x; 1.0313x over previous
#include <cuda_runtime.h>
#include <cstdint>

// BaseVectorQuantizer, exact: dist_k = fp32( fp32(||x||^2+||e_k||^2) - 2*dot ).
// V=2, row-major codebook in smem. Loads forced to true LDS.128 via
// ld.shared.v4.b32 (+ mov.b64 repack on the idle ALU pipe) to test whether
// the previous v2.u64 form was splitting into 2x LDS.64 (8.25 cyc observed).
// Argmin as u64 (distbits<<32|k) integer min on the ALU pipe.
// FMA values and chain order bit-identical to the R13 zero-flip chain.

#define NUM_K 1024
#define DIM   64
#define CHUNK 256
#define TPB   128
#define HW    4096
#define NVEC  131072
#define VPB   256

typedef unsigned long long ull_t;

__device__ float g_esq[NUM_K];

__global__ void esq_kernel(const float* __restrict__ cb) {
    int k = blockIdx.x * blockDim.x + threadIdx.x;
    if (k < NUM_K) {
        float s = 0.f;
        #pragma unroll
        for (int i = 0; i < DIM; i++) {
            float v = cb[k * DIM + i];
            s = __fadd_rn(s, __fmul_rn(v, v));
        }
        g_esq[k] = s;
    }
}

__global__ __launch_bounds__(TPB, 2) void vq_kernel(const float* __restrict__ x_in,
                                                    const float* __restrict__ cb,
                                                    float* __restrict__ out) {
    __shared__ __align__(16) float se[CHUNK * DIM];   // 64 KB row-major
    __shared__ float sesq[CHUNK];

    const int t    = threadIdx.x;
    const int base = blockIdx.x * VPB;
    const int b    = base >> 12;
    const int sA   = (base & (HW - 1)) + t;
    const float* xpA = x_in + (size_t)b * (DIM * HW) + sA;
    const float* xpB = xpA + TPB;

    // x for both vectors as natural packed f32x2 dim-pairs; xsq sequential fp32
    ull_t xA2[DIM / 2], xB2[DIM / 2];
    float xsqA = 0.f, xsqB = 0.f;
    #pragma unroll
    for (int p = 0; p < DIM / 2; p++) {
        float a0f = xpA[(2 * p) * HW], a1f = xpA[(2 * p + 1) * HW];
        float c0f = xpB[(2 * p) * HW], c1f = xpB[(2 * p + 1) * HW];
        xsqA = __fadd_rn(xsqA, __fmul_rn(a0f, a0f));
        xsqA = __fadd_rn(xsqA, __fmul_rn(a1f, a1f));
        xsqB = __fadd_rn(xsqB, __fmul_rn(c0f, c0f));
        xsqB = __fadd_rn(xsqB, __fmul_rn(c1f, c1f));
        asm("mov.b64 %0, {%1, %2};" : "=l"(xA2[p]) : "f"(a0f), "f"(a1f));
        asm("mov.b64 %0, {%1, %2};" : "=l"(xB2[p]) : "f"(c0f), "f"(c1f));
    }

    uint32_t se_base;
    asm("{ .reg .u64 t; cvta.to.shared.u64 t, %1; cvt.u32.u64 %0, t; }"
        : "=r"(se_base) : "l"(se));

    // u64 argmin keys: (float bits of dist << 32) | k.  dist > 0 always
    // (xsq ~ chi2_64 >> |2*dot| <= 0.08), so bit order == float order, and
    // integer min == lexicographic (dist, k) == first-min tie-break.
    ull_t keyA = ~0ull, keyB = ~0ull;

    for (int c = 0; c < NUM_K / CHUNK; c++) {
        __syncthreads();
        const float4* src = reinterpret_cast<const float4*>(cb + c * CHUNK * DIM);
        float4* dst = reinterpret_cast<float4*>(se);
        #pragma unroll
        for (int j = 0; j < (CHUNK * DIM / 4) / TPB; j++)
            dst[j * TPB + t] = src[j * TPB + t];
        #pragma unroll
        for (int j = 0; j < CHUNK / TPB; j++)
            sesq[j * TPB + t] = g_esq[c * CHUNK + j * TPB + t];
        __syncthreads();

        #pragma unroll 2
        for (int k = 0; k < CHUNK; k++) {
            ull_t a0 = 0ull, a1 = 0ull, b0 = 0ull, b1 = 0ull;
            const uint32_t addr = se_base + k * (DIM * 4);
            #pragma unroll
            for (int d4 = 0; d4 < DIM / 4; d4++) {
                uint32_t f0, f1, f2, f3;
                asm("ld.shared.v4.b32 {%0,%1,%2,%3}, [%4];"   // true LDS.128
                    : "=r"(f0), "=r"(f1), "=r"(f2), "=r"(f3)
                    : "r"(addr + d4 * 16));
                ull_t e0, e1;                                  // repack on ALU pipe
                asm("mov.b64 %0, {%1, %2};" : "=l"(e0) : "r"(f0), "r"(f1));
                asm("mov.b64 %0, {%1, %2};" : "=l"(e1) : "r"(f2), "r"(f3));
                asm("fma.rn.f32x2 %0, %1, %2, %0;" : "+l"(a0) : "l"(xA2[2 * d4]),     "l"(e0));
                asm("fma.rn.f32x2 %0, %1, %2, %0;" : "+l"(a1) : "l"(xA2[2 * d4 + 1]), "l"(e1));
                asm("fma.rn.f32x2 %0, %1, %2, %0;" : "+l"(b0) : "l"(xB2[2 * d4]),     "l"(e0));
                asm("fma.rn.f32x2 %0, %1, %2, %0;" : "+l"(b1) : "l"(xB2[2 * d4 + 1]), "l"(e1));
            }
            ull_t sa, sb;
            asm("add.rn.f32x2 %0, %1, %2;" : "=l"(sa) : "l"(a0), "l"(a1));
            asm("add.rn.f32x2 %0, %1, %2;" : "=l"(sb) : "l"(b0), "l"(b1));
            float alo, ahi, blo, bhi;
            asm("mov.b64 {%0, %1}, %2;" : "=f"(alo), "=f"(ahi) : "l"(sa));
            asm("mov.b64 {%0, %1}, %2;" : "=f"(blo), "=f"(bhi) : "l"(sb));
            const float esq  = sesq[k];
            const float dotA = __fadd_rn(alo, ahi);
            const float dotB = __fadd_rn(blo, bhi);
            // dist = round(T - 2*dot), T = round(xsq+esq); 2*dot exact ->
            // fmaf(-2,dot,T) rounds once == reference fsub(T, 2dot)
            const float dA = fmaf(-2.f, dotA, __fadd_rn(xsqA, esq));
            const float dB = fmaf(-2.f, dotB, __fadd_rn(xsqB, esq));
            const int kk = c * CHUNK + k;
            ull_t nkA, nkB;
            asm("mov.b64 %0, {%1, %2};" : "=l"(nkA) : "r"((uint32_t)kk), "r"(__float_as_uint(dA)));
            asm("mov.b64 %0, {%1, %2};" : "=l"(nkB) : "r"((uint32_t)kk), "r"(__float_as_uint(dB)));
            keyA = (nkA < keyA) ? nkA : keyA;      // integer min on ALU pipe
            keyB = (nkB < keyB) ? nkB : keyB;
        }
    }

    const int bkA = (int)(uint32_t)keyA;
    const int bkB = (int)(uint32_t)keyB;

    // STE epilogue: out = x + (e - x) fp32, BCHW scatter
    const float4* rowA = reinterpret_cast<const float4*>(cb + (size_t)bkA * DIM);
    const float4* rowB = reinterpret_cast<const float4*>(cb + (size_t)bkB * DIM);
    float* opA = out + (size_t)b * (DIM * HW) + sA;
    float* opB = opA + TPB;
    #pragma unroll
    for (int j = 0; j < DIM / 4; j++) {
        float4 qA = __ldg(&rowA[j]);
        float4 qB = __ldg(&rowB[j]);
        float a0f, a1f, a2f, a3f, c0f, c1f, c2f, c3f;
        asm("mov.b64 {%0, %1}, %2;" : "=f"(a0f), "=f"(a1f) : "l"(xA2[2 * j]));
        asm("mov.b64 {%0, %1}, %2;" : "=f"(a2f), "=f"(a3f) : "l"(xA2[2 * j + 1]));
        asm("mov.b64 {%0, %1}, %2;" : "=f"(c0f), "=f"(c1f) : "l"(xB2[2 * j]));
        asm("mov.b64 {%0, %1}, %2;" : "=f"(c2f), "=f"(c3f) : "l"(xB2[2 * j + 1]));
        opA[(4 * j + 0) * HW] = __fadd_rn(a0f, __fsub_rn(qA.x, a0f));
        opA[(4 * j + 1) * HW] = __fadd_rn(a1f, __fsub_rn(qA.y, a1f));
        opA[(4 * j + 2) * HW] = __fadd_rn(a2f, __fsub_rn(qA.z, a2f));
        opA[(4 * j + 3) * HW] = __fadd_rn(a3f, __fsub_rn(qA.w, a3f));
        opB[(4 * j + 0) * HW] = __fadd_rn(c0f, __fsub_rn(qB.x, c0f));
        opB[(4 * j + 1) * HW] = __fadd_rn(c1f, __fsub_rn(qB.y, c1f));
        opB[(4 * j + 2) * HW] = __fadd_rn(c2f, __fsub_rn(qB.z, c2f));
        opB[(4 * j + 3) * HW] = __fadd_rn(c3f, __fsub_rn(qB.w, c3f));
    }
}

extern "C" void kernel_launch(void* const* d_in, const int* in_sizes, int n_in,
                              void* d_out, int out_size) {
    const float* x  = (const float*)d_in[0];
    const float* cb = (const float*)d_in[1];
    if (n_in >= 2 && in_sizes[0] == NUM_K * DIM && in_sizes[1] == NVEC * DIM) {
        const float* t = x; x = cb; cb = t;
    }
    float* out = (float*)d_out;

    esq_kernel<<<(NUM_K + 127) / 128, 128>>>(cb);
    vq_kernel<<<NVEC / VPB, TPB>>>(x, cb, out);
}